// round 1
// baseline (speedup 1.0000x reference)
#include <cuda_runtime.h>
#include <cstdint>

#define Bb 8
#define Ss 8192
#define Dd 512
#define Vv 256
#define Ll 12
#define BS (Bb*Ss)        /* 65536 */
#define TWO_D 1024
#define NCH 32
#define CHLEN (Ss/NCH)    /* 256 */

// Scratch (allocation-free: device globals)
__device__ float g_x[BS*Dd];        // residual stream, 134MB
__device__ float g_h[BS*Dd];        // LN output, 134MB
__device__ float g_hg[BS*TWO_D];    // GEMM output (hidden|gate), 268MB
__device__ float g_embT[Dd*Vv];     // transposed embedding, 512KB

// ---------------------------------------------------------------------------
// emb [V,D] -> embT [D,V]
__global__ void transpose_emb_kernel(const float* __restrict__ emb) {
    int k = blockIdx.x;          // 0..511
    int n = threadIdx.x;         // 0..255
    g_embT[k*Vv + n] = emb[n*Dd + k];
}

// x[r] = emb[tokens[r]]
__global__ void embed_kernel(const int* __restrict__ tokens,
                             const float* __restrict__ emb) {
    int r = blockIdx.x;
    int t = threadIdx.x;         // 128 threads, float4 each
    int tok = tokens[r];
    float4 v = ((const float4*)(emb + (size_t)tok*Dd))[t];
    ((float4*)(g_x + (size_t)r*Dd))[t] = v;
}

// h[r] = LN(x[r]) * g + b      (one block / row, 128 threads, float4)
__global__ void ln_kernel(const float* __restrict__ gvec,
                          const float* __restrict__ bvec) {
    __shared__ float ss[4], sq[4];
    int r = blockIdx.x;
    int t = threadIdx.x;
    float4 v = ((const float4*)(g_x + (size_t)r*Dd))[t];
    float s = v.x + v.y + v.z + v.w;
    float q = v.x*v.x + v.y*v.y + v.z*v.z + v.w*v.w;
    #pragma unroll
    for (int o = 16; o; o >>= 1) {
        s += __shfl_xor_sync(0xffffffffu, s, o);
        q += __shfl_xor_sync(0xffffffffu, q, o);
    }
    if ((t & 31) == 0) { ss[t >> 5] = s; sq[t >> 5] = q; }
    __syncthreads();
    s = ss[0] + ss[1] + ss[2] + ss[3];
    q = sq[0] + sq[1] + sq[2] + sq[3];
    float mu  = s * (1.0f/Dd);
    float var = q * (1.0f/Dd) - mu*mu;
    float inv = rsqrtf(var + 1e-5f);
    float4 gg = ((const float4*)gvec)[t];
    float4 bb = ((const float4*)bvec)[t];
    float4 o;
    o.x = (v.x - mu)*inv*gg.x + bb.x;
    o.y = (v.y - mu)*inv*gg.y + bb.y;
    o.z = (v.z - mu)*inv*gg.z + bb.z;
    o.w = (v.w - mu)*inv*gg.w + bb.w;
    ((float4*)(g_h + (size_t)r*Dd))[t] = o;
}

// ---------------------------------------------------------------------------
// fp32 SIMT GEMM: C[M,N] = A[M,K] @ B[K,N]; BM=BN=128, BK=8, 256 thr, 8x8/thr
__device__ __forceinline__ void sgemm128(const float* __restrict__ A,
                                         const float* __restrict__ Bm,
                                         float* __restrict__ C,
                                         int N, int K) {
    __shared__ float As[8][128];
    __shared__ float Bs[8][128];
    int tid = threadIdx.x;
    int bx = blockIdx.x, by = blockIdx.y;
    int arow = tid >> 1;             // 0..127
    int acol = (tid & 1) << 2;       // 0 or 4
    int brow = tid >> 5;             // 0..7
    int bcol = (tid & 31) << 2;      // 0..124
    const float* Ab = A + (size_t)(by*128)*K;
    const float* Bp = Bm + bx*128;
    int tx = tid & 15, ty = tid >> 4;
    float acc[8][8] = {};
    for (int k0 = 0; k0 < K; k0 += 8) {
        float4 a4 = *(const float4*)(Ab + (size_t)arow*K + k0 + acol);
        As[acol+0][arow] = a4.x; As[acol+1][arow] = a4.y;
        As[acol+2][arow] = a4.z; As[acol+3][arow] = a4.w;
        float4 b4 = *(const float4*)(Bp + (size_t)(k0+brow)*N + bcol);
        *(float4*)&Bs[brow][bcol] = b4;
        __syncthreads();
        #pragma unroll
        for (int k = 0; k < 8; k++) {
            float ra[8], rb[8];
            #pragma unroll
            for (int i = 0; i < 8; i++) ra[i] = As[k][ty*8 + i];
            #pragma unroll
            for (int j = 0; j < 8; j++) rb[j] = Bs[k][tx*8 + j];
            #pragma unroll
            for (int i = 0; i < 8; i++)
                #pragma unroll
                for (int j = 0; j < 8; j++)
                    acc[i][j] += ra[i]*rb[j];
        }
        __syncthreads();
    }
    float* Cb = C + (size_t)(by*128 + ty*8)*N + bx*128 + tx*8;
    #pragma unroll
    for (int i = 0; i < 8; i++) {
        *(float4*)(Cb + (size_t)i*N + 0) = make_float4(acc[i][0],acc[i][1],acc[i][2],acc[i][3]);
        *(float4*)(Cb + (size_t)i*N + 4) = make_float4(acc[i][4],acc[i][5],acc[i][6],acc[i][7]);
    }
}

__global__ void gemm_layer_kernel(const float* __restrict__ Wl) {
    sgemm128(g_h, Wl, g_hg, TWO_D, Dd);     // hg = h @ W[i]
}
__global__ void gemm_logits_kernel(float* __restrict__ out) {
    sgemm128(g_h, g_embT, out, Vv, Dd);     // logits = ln(x) @ emb^T
}

// ---------------------------------------------------------------------------
// min-GRU scan + residual. Linear recurrence h_t = c*h_{t-1} + v (exact
// equivalent of the log-space heinsen scan: c in (0,1), v > 0 bounded).
// Block = 32 d-channels x 32 sequence chunks (1024 thr); one (batch, d-tile).
// Phase A: per-chunk local scan, writing (h_local, c_prod) in place into hg.
// Phase B: cross-chunk prefix via shared memory.
// Phase C: fixup h = h_local + c_prod * h_prefix;  x += h.
__global__ void scan_kernel() {
    __shared__ float sc[NCH][32];
    __shared__ float sh[NCH][32];
    int lane = threadIdx.x & 31;
    int ch   = threadIdx.x >> 5;
    int d    = blockIdx.x*32 + lane;
    int r0   = blockIdx.y*Ss + ch*CHLEN;

    float cprod = 1.0f, h = 0.0f;
    size_t idx = (size_t)r0*TWO_D + d;
    #pragma unroll 4
    for (int t = 0; t < CHLEN; t++) {
        float hid  = g_hg[idx];
        float gate = g_hg[idx + Dd];
        gate = fminf(fmaxf(gate, -60.0f), 60.0f);
        float e = __expf(-gate);
        float rinv = __fdividef(1.0f, 1.0f + e);
        float z = rinv;              // sigmoid(gate)
        float c = e * rinv;          // sigmoid(-gate) = 1 - z
        float gv;
        if (hid >= 0.0f) gv = hid + 0.5f;
        else {
            float hc = fmaxf(hid, -60.0f);
            gv = __fdividef(1.0f, 1.0f + __expf(-hc));
        }
        float v = z * gv;
        h = c*h + v;
        cprod *= c;
        g_hg[idx]      = h;          // local scan value
        g_hg[idx + Dd] = cprod;      // running coefficient product
        idx += TWO_D;
    }
    sc[ch][lane] = cprod;
    sh[ch][lane] = h;
    __syncthreads();

    float hpre = 0.0f;
    for (int j = 0; j < ch; j++) hpre = sc[j][lane]*hpre + sh[j][lane];

    idx = (size_t)r0*TWO_D + d;
    size_t xidx = (size_t)r0*Dd + d;
    #pragma unroll 4
    for (int t = 0; t < CHLEN; t++) {
        float hloc = g_hg[idx];
        float cp   = g_hg[idx + Dd];
        g_x[xidx] += hloc + cp*hpre;   // residual add
        idx  += TWO_D;
        xidx += Dd;
    }
}

// ---------------------------------------------------------------------------
extern "C" void kernel_launch(void* const* d_in, const int* in_sizes, int n_in,
                              void* d_out, int out_size) {
    const int*   tokens = (const int*)  d_in[0];
    const float* emb    = (const float*)d_in[1];
    const float* ln_g   = (const float*)d_in[2];
    const float* ln_b   = (const float*)d_in[3];
    const float* W      = (const float*)d_in[4];
    const float* norm_g = (const float*)d_in[5];
    const float* norm_b = (const float*)d_in[6];
    float* out = (float*)d_out;

    transpose_emb_kernel<<<Dd, Vv>>>(emb);
    embed_kernel<<<BS, 128>>>(tokens, emb);

    for (int i = 0; i < Ll; i++) {
        ln_kernel<<<BS, 128>>>(ln_g + i*Dd, ln_b + i*Dd);
        gemm_layer_kernel<<<dim3(TWO_D/128, BS/128), 256>>>(W + (size_t)i*Dd*TWO_D);
        scan_kernel<<<dim3(Dd/32, Bb), NCH*32>>>();
    }

    ln_kernel<<<BS, 128>>>(norm_g, norm_b);
    gemm_logits_kernel<<<dim3(Vv/128, BS/128), 256>>>(out);
}

// round 3
// speedup vs baseline: 2.2558x; 2.2558x over previous
#include <cuda_runtime.h>
#include <cuda_bf16.h>
#include <cstdint>

#define Bb 8
#define Ss 8192
#define Dd 512
#define Vv 256
#define Ll 12
#define BS (Bb*Ss)        /* 65536 */
#define TWO_D 1024
#define NCH 32
#define CHLEN (Ss/NCH)    /* 256 */

// ---------------- scratch (allocation-free) ----------------
__device__ float         g_x [(size_t)BS*Dd];     // residual stream fp32
__device__ __nv_bfloat16 g_hb[(size_t)BS*TWO_D];  // LN out split: cols [0,512)=hi, [512,1024)=lo
__device__ float         g_hg[(size_t)BS*TWO_D];  // GEMM out (hidden|gate) fp32
__device__ __nv_bfloat16 g_w [(size_t)Ll*2*TWO_D*Dd]; // W^T split: [(l*2+p)*1024 + n][k]
__device__ __nv_bfloat16 g_e [(size_t)2*Vv*Dd];       // emb split: [p*256 + n][k]

// ---------------- PTX helpers ----------------
__device__ __forceinline__ uint32_t smem_u32(const void* p) {
    uint32_t a;
    asm("{ .reg .u64 t; cvta.to.shared.u64 t, %1; cvt.u32.u64 %0, t; }" : "=r"(a) : "l"(p));
    return a;
}
#define CP_ASYNC16(d,s) asm volatile("cp.async.cg.shared.global [%0], [%1], 16;"::"r"(d),"l"(s):"memory")
#define CP_COMMIT()     asm volatile("cp.async.commit_group;":::"memory")
#define CP_WAIT(n)      asm volatile("cp.async.wait_group %0;"::"n"(n):"memory")

#define LDSM_X4(r0,r1,r2,r3,a) \
    asm volatile("ldmatrix.sync.aligned.m8n8.x4.shared.b16 {%0,%1,%2,%3}, [%4];" \
        : "=r"(r0),"=r"(r1),"=r"(r2),"=r"(r3) : "r"(a))

#define MMA16816(d,a,b) \
    asm volatile("mma.sync.aligned.m16n8k16.row.col.f32.bf16.bf16.f32 " \
        "{%0,%1,%2,%3},{%4,%5,%6,%7},{%8,%9},{%0,%1,%2,%3};" \
        : "+f"((d)[0]),"+f"((d)[1]),"+f"((d)[2]),"+f"((d)[3]) \
        : "r"((a)[0]),"r"((a)[1]),"r"((a)[2]),"r"((a)[3]),"r"((b)[0]),"r"((b)[1]))

// swizzled smem byte offset within a tile of 128B rows
__device__ __forceinline__ uint32_t sw(uint32_t r, uint32_t cb) {
    return r*128u + (cb ^ ((r & 7u) << 4));
}

// ---------------- small prep kernels ----------------
__global__ void wsplit_kernel(const float* __restrict__ W) {
    int k = threadIdx.x, n = blockIdx.x, l = blockIdx.y;
    float w = W[((size_t)l*Dd + k)*TWO_D + n];
    __nv_bfloat16 hi = __float2bfloat16(w);
    float lo = w - __bfloat162float(hi);
    g_w[(((size_t)l*2+0)*TWO_D + n)*Dd + k] = hi;
    g_w[(((size_t)l*2+1)*TWO_D + n)*Dd + k] = __float2bfloat16(lo);
}
__global__ void esplit_kernel(const float* __restrict__ emb) {
    int k = threadIdx.x, n = blockIdx.x;
    float w = emb[(size_t)n*Dd + k];
    __nv_bfloat16 hi = __float2bfloat16(w);
    float lo = w - __bfloat162float(hi);
    g_e[(size_t)n*Dd + k] = hi;
    g_e[((size_t)Vv + n)*Dd + k] = __float2bfloat16(lo);
}
__global__ void embed_kernel(const int* __restrict__ tokens,
                             const float* __restrict__ emb) {
    int r = blockIdx.x, t = threadIdx.x;
    int tok = tokens[r];
    float4 v = ((const float4*)(emb + (size_t)tok*Dd))[t];
    ((float4*)(g_x + (size_t)r*Dd))[t] = v;
}

// LN(x)*g+b -> bf16 split into g_hb
__global__ void ln_kernel(const float* __restrict__ gvec,
                          const float* __restrict__ bvec) {
    __shared__ float ss[4], sq[4];
    int r = blockIdx.x, t = threadIdx.x;
    float4 v = ((const float4*)(g_x + (size_t)r*Dd))[t];
    float s = v.x + v.y + v.z + v.w;
    float q = v.x*v.x + v.y*v.y + v.z*v.z + v.w*v.w;
    #pragma unroll
    for (int o = 16; o; o >>= 1) {
        s += __shfl_xor_sync(0xffffffffu, s, o);
        q += __shfl_xor_sync(0xffffffffu, q, o);
    }
    if ((t & 31) == 0) { ss[t >> 5] = s; sq[t >> 5] = q; }
    __syncthreads();
    s = ss[0]+ss[1]+ss[2]+ss[3];
    q = sq[0]+sq[1]+sq[2]+sq[3];
    float mu = s * (1.0f/Dd);
    float inv = rsqrtf(q*(1.0f/Dd) - mu*mu + 1e-5f);
    float4 gg = ((const float4*)gvec)[t];
    float4 bb = ((const float4*)bvec)[t];
    float o0 = (v.x-mu)*inv*gg.x + bb.x;
    float o1 = (v.y-mu)*inv*gg.y + bb.y;
    float o2 = (v.z-mu)*inv*gg.z + bb.z;
    float o3 = (v.w-mu)*inv*gg.w + bb.w;
    __nv_bfloat16 h0=__float2bfloat16(o0), h1=__float2bfloat16(o1),
                  h2=__float2bfloat16(o2), h3=__float2bfloat16(o3);
    __nv_bfloat16 l0=__float2bfloat16(o0-__bfloat162float(h0));
    __nv_bfloat16 l1=__float2bfloat16(o1-__bfloat162float(h1));
    __nv_bfloat16 l2=__float2bfloat16(o2-__bfloat162float(h2));
    __nv_bfloat16 l3=__float2bfloat16(o3-__bfloat162float(h3));
    size_t base = (size_t)r*TWO_D;
    *(__nv_bfloat162*)(g_hb+base+4*t)       = __halves2bfloat162(h0,h1);
    *(__nv_bfloat162*)(g_hb+base+4*t+2)     = __halves2bfloat162(h2,h3);
    *(__nv_bfloat162*)(g_hb+base+Dd+4*t)    = __halves2bfloat162(l0,l1);
    *(__nv_bfloat162*)(g_hb+base+Dd+4*t+2)  = __halves2bfloat162(l2,l3);
}

// ---------------- split-bf16 GEMM via mma.sync ----------------
// C[128 x 256 tile] = sum over 24 K-chunks of 64:
//   phase (i>>3): 0=(hi,hi) 1=(hi,lo) 2=(lo,hi);  kc = i&7 selects 64-col slab.
#define STAGES 4
#define A_STG 16384                 /* 128 x 64 bf16 */
#define B_STG 32768                 /* 256 x 64 bf16 */
#define STG_B (A_STG + B_STG)       /* 49152 */
#define GEMM_SMEM (STAGES*STG_B)    /* 196608 */
#define NCHUNK 24

__global__ void __launch_bounds__(256,1) gemm3_kernel(
    const __nv_bfloat16* __restrict__ Bbase, int bpr,
    float* __restrict__ C, int ldc)
{
    extern __shared__ char smem[];
    uint32_t sb = smem_u32(smem);
    int tid = threadIdx.x;
    int m0 = blockIdx.y * 128;
    int n0 = blockIdx.x * 256;

    // loader mapping
    int rr  = tid >> 3;              // 0..31
    int c8  = (tid & 7) * 8;         // bf16 col offset (16B granules)
    uint32_t cb = (uint32_t)(tid & 7) * 16;

    auto load_chunk = [&](int i) {
        int s = i & (STAGES-1);
        int ph = i >> 3, kc = i & 7;
        int pa = (ph == 2), pb = (ph == 1);
        uint32_t stA = sb + s*STG_B;
        uint32_t stB = stA + A_STG;
        const __nv_bfloat16* gA = g_hb + (size_t)(m0+rr)*TWO_D + pa*Dd + kc*64 + c8;
        #pragma unroll
        for (int j = 0; j < 4; j++)
            CP_ASYNC16(stA + sw(rr + j*32, cb), gA + (size_t)j*32*TWO_D);
        const __nv_bfloat16* gB = Bbase + (size_t)(pb*bpr + n0 + rr)*Dd + kc*64 + c8;
        #pragma unroll
        for (int j = 0; j < 8; j++)
            CP_ASYNC16(stB + sw(rr + j*32, cb), gB + (size_t)j*32*Dd);
        CP_COMMIT();
    };

    // prologue: 3 chunks in flight
    load_chunk(0); load_chunk(1); load_chunk(2);

    int wid = tid >> 5, lane = tid & 31;
    int wm = wid >> 2;               // 0..1
    int wn = wid & 3;                // 0..3
    float acc[4][8][4];
    #pragma unroll
    for (int f = 0; f < 4; f++)
        #pragma unroll
        for (int g = 0; g < 8; g++)
            #pragma unroll
            for (int q = 0; q < 4; q++) acc[f][g][q] = 0.0f;

    // precomputed ldmatrix row/col fragments
    uint32_t a_row = (uint32_t)(wm*64 + (lane & 15));
    uint32_t a_cbh = (uint32_t)((lane >> 4) << 4);
    uint32_t b_row = (uint32_t)(wn*64 + ((lane >> 4) << 3) + (lane & 7));
    uint32_t b_cbh = (uint32_t)((lane & 8) << 1);

    for (int i = 0; i < NCHUNK; i++) {
        if (i + 3 < NCHUNK) load_chunk(i + 3);
        CP_WAIT(3);
        __syncthreads();
        int s = i & (STAGES-1);
        uint32_t stA = sb + s*STG_B;
        uint32_t stB = stA + A_STG;
        #pragma unroll
        for (int kk = 0; kk < 4; kk++) {
            uint32_t a[4][4];
            #pragma unroll
            for (int f = 0; f < 4; f++) {
                uint32_t r = a_row + f*16;
                LDSM_X4(a[f][0],a[f][1],a[f][2],a[f][3], stA + sw(r, kk*32 + a_cbh));
            }
            uint32_t b[8][2];
            #pragma unroll
            for (int g = 0; g < 4; g++) {
                uint32_t r = b_row + g*16;
                LDSM_X4(b[2*g][0],b[2*g][1],b[2*g+1][0],b[2*g+1][1],
                        stB + sw(r, kk*32 + b_cbh));
            }
            #pragma unroll
            for (int f = 0; f < 4; f++)
                #pragma unroll
                for (int g = 0; g < 8; g++)
                    MMA16816(acc[f][g], a[f], b[g]);
        }
        __syncthreads();
    }

    // epilogue: direct fp32 stores
    #pragma unroll
    for (int f = 0; f < 4; f++) {
        int row = m0 + wm*64 + 16*f + (lane >> 2);
        float* c0 = C + (size_t)row*ldc + n0 + wn*64 + (lane & 3)*2;
        float* c1 = c0 + (size_t)8*ldc;
        #pragma unroll
        for (int g = 0; g < 8; g++) {
            *(float2*)(c0 + g*8) = make_float2(acc[f][g][0], acc[f][g][1]);
            *(float2*)(c1 + g*8) = make_float2(acc[f][g][2], acc[f][g][3]);
        }
    }
}

// ---------------- min-GRU scan + residual ----------------
__global__ void scan_kernel() {
    __shared__ float sc[NCH][32];
    __shared__ float sh[NCH][32];
    int lane = threadIdx.x & 31;
    int ch   = threadIdx.x >> 5;
    int d    = blockIdx.x*32 + lane;
    int r0   = blockIdx.y*Ss + ch*CHLEN;

    float cprod = 1.0f, h = 0.0f;
    size_t idx = (size_t)r0*TWO_D + d;
    #pragma unroll 4
    for (int t = 0; t < CHLEN; t++) {
        float hid  = g_hg[idx];
        float gate = g_hg[idx + Dd];
        gate = fminf(fmaxf(gate, -60.0f), 60.0f);
        float e = __expf(-gate);
        float rinv = __fdividef(1.0f, 1.0f + e);
        float z = rinv;
        float c = e * rinv;
        float gv;
        if (hid >= 0.0f) gv = hid + 0.5f;
        else {
            float hc = fmaxf(hid, -60.0f);
            gv = __fdividef(1.0f, 1.0f + __expf(-hc));
        }
        float v = z * gv;
        h = c*h + v;
        cprod *= c;
        g_hg[idx]      = h;
        g_hg[idx + Dd] = cprod;
        idx += TWO_D;
    }
    sc[ch][lane] = cprod;
    sh[ch][lane] = h;
    __syncthreads();

    float hpre = 0.0f;
    for (int j = 0; j < ch; j++) hpre = sc[j][lane]*hpre + sh[j][lane];

    idx = (size_t)r0*TWO_D + d;
    size_t xidx = (size_t)r0*Dd + d;
    #pragma unroll 4
    for (int t = 0; t < CHLEN; t++) {
        float hloc = g_hg[idx];
        float cp   = g_hg[idx + Dd];
        g_x[xidx] += hloc + cp*hpre;
        idx  += TWO_D;
        xidx += Dd;
    }
}

// ---------------------------------------------------------------------------
extern "C" void kernel_launch(void* const* d_in, const int* in_sizes, int n_in,
                              void* d_out, int out_size) {
    const int*   tokens = (const int*)  d_in[0];
    const float* emb    = (const float*)d_in[1];
    const float* ln_g   = (const float*)d_in[2];
    const float* ln_b   = (const float*)d_in[3];
    const float* W      = (const float*)d_in[4];
    const float* norm_g = (const float*)d_in[5];
    const float* norm_b = (const float*)d_in[6];
    float* out = (float*)d_out;

    void *p_w = nullptr, *p_e = nullptr, *p_hg = nullptr;
    cudaGetSymbolAddress(&p_w,  g_w);
    cudaGetSymbolAddress(&p_e,  g_e);
    cudaGetSymbolAddress(&p_hg, g_hg);
    cudaFuncSetAttribute(gemm3_kernel, cudaFuncAttributeMaxDynamicSharedMemorySize, GEMM_SMEM);

    wsplit_kernel<<<dim3(TWO_D, Ll), Dd>>>(W);
    esplit_kernel<<<Vv, Dd>>>(emb);
    embed_kernel<<<BS, 128>>>(tokens, emb);

    for (int l = 0; l < Ll; l++) {
        ln_kernel<<<BS, 128>>>(ln_g + l*Dd, ln_b + l*Dd);
        gemm3_kernel<<<dim3(TWO_D/256, BS/128), 256, GEMM_SMEM>>>(
            (const __nv_bfloat16*)p_w + (size_t)l*2*TWO_D*Dd, TWO_D,
            (float*)p_hg, TWO_D);
        scan_kernel<<<dim3(Dd/32, Bb), NCH*32>>>();
    }

    ln_kernel<<<BS, 128>>>(norm_g, norm_b);
    gemm3_kernel<<<dim3(1, BS/128), 256, GEMM_SMEM>>>(
        (const __nv_bfloat16*)p_e, Vv, out, Vv);
}